// round 4
// baseline (speedup 1.0000x reference)
#include <cuda_runtime.h>
#include <cuda_bf16.h>
#include <cuda_fp8.h>
#include <cstdint>

// ============================================================================
// ContrastiveLoss (N=4096, D=256, tau=0.1)
//   z = normalize(concat(x1,x2)) -> e4m3
//   denom[r] = sum_j exp(mask * (z_r . z_j) / tau)   (diag -> exp(0)=1)
//   loss = mean_r( log(denom[r]) - pos[r]/tau )      (pos in exact fp32)
// Symmetric-triangle fused FP8 mma.sync GEMM: only tiles J>=I computed;
// off-diagonal tiles feed row sums (strip I) AND column sums (strip J).
// ============================================================================

#define TAU_INV 10.0f
static constexpr int NROWS = 4096;
static constexpr int TWO_N = 8192;
static constexpr int D     = 256;          // K
static constexpr int BM    = 128;
static constexpr int BN    = 128;
static constexpr int NSTRIP = TWO_N / BM;            // 64
static constexpr int NUM_TILES = NSTRIP * (NSTRIP + 1) / 2;   // 2080
static constexpr int NUM_CTAS  = 148;
static constexpr int K_STEPS   = D / 32;             // 8 (fp8 k=32 per mma)

// SMEM tiles: [128 rows][256 k] fp8, padded row stride 272 B (17 x 16B)
static constexpr int TSTRIDE_B = 272;
static constexpr int TILE_BYTES = BM * TSTRIDE_B;     // 34816
static constexpr int SMEM_TOTAL = 3 * TILE_BYTES;     // A + B0 + B1 = 104448

// ---------------- device scratch (allocation-free) --------------------------
__device__ unsigned char g_z8[TWO_N * D];   // e4m3, row-major [8192][256]  (2 MB)
__device__ float    g_pos[NROWS];
__device__ float    g_denom[TWO_N];
__device__ unsigned g_done;

// ---------------- PTX helpers ----------------------------------------------
__device__ __forceinline__ uint32_t smem_to_u32(const void* p) {
    uint32_t a;
    asm("{ .reg .u64 t; cvta.to.shared.u64 t, %1; cvt.u32.u64 %0, t; }"
        : "=r"(a) : "l"(p));
    return a;
}

__device__ __forceinline__ void cp_async16(uint32_t dst, const void* src) {
    asm volatile("cp.async.cg.shared.global [%0], [%1], 16;"
                 :: "r"(dst), "l"(src) : "memory");
}
#define CP_COMMIT() asm volatile("cp.async.commit_group;" ::: "memory")
#define CP_WAIT0()  asm volatile("cp.async.wait_group 0;" ::: "memory")
#define CP_WAIT1()  asm volatile("cp.async.wait_group 1;" ::: "memory")

__device__ __forceinline__ void ldsm_x4(uint32_t* r, uint32_t addr) {
    asm volatile("ldmatrix.sync.aligned.m8n8.x4.shared.b16 {%0,%1,%2,%3}, [%4];"
                 : "=r"(r[0]), "=r"(r[1]), "=r"(r[2]), "=r"(r[3]) : "r"(addr));
}
__device__ __forceinline__ void ldsm_x2(uint32_t* r, uint32_t addr) {
    asm volatile("ldmatrix.sync.aligned.m8n8.x2.shared.b16 {%0,%1}, [%2];"
                 : "=r"(r[0]), "=r"(r[1]) : "r"(addr));
}

// FP8 e4m3 MMA: m16n8k32, fragments are the bf16-k16 fragments with each b16
// element holding 2 fp8 (so ldmatrix b16 addressing carries over unchanged).
#define MMA16832F8(d, a, b) \
    asm volatile( \
        "mma.sync.aligned.m16n8k32.row.col.f32.e4m3.e4m3.f32 " \
        "{%0,%1,%2,%3}, {%4,%5,%6,%7}, {%8,%9}, {%0,%1,%2,%3};" \
        : "+f"((d)[0]), "+f"((d)[1]), "+f"((d)[2]), "+f"((d)[3]) \
        : "r"((a)[0]), "r"((a)[1]), "r"((a)[2]), "r"((a)[3]), \
          "r"((b)[0]), "r"((b)[1]))

__device__ __forceinline__ uint32_t pack_e4m3x4(float v0, float v1, float v2, float v3) {
    __nv_fp8x2_storage_t lo =
        __nv_cvt_float2_to_fp8x2(make_float2(v0, v1), __NV_SATFINITE, __NV_E4M3);
    __nv_fp8x2_storage_t hi =
        __nv_cvt_float2_to_fp8x2(make_float2(v2, v3), __NV_SATFINITE, __NV_E4M3);
    return (uint32_t)lo | ((uint32_t)hi << 16);
}

// Balanced triangle enumeration: pair p in [0,32) = strip p (64-p tiles,
// J=p..63) followed by strip 63-p (p+1 tiles, J=63-p..63). 65 tiles per pair.
__device__ __forceinline__ void decode_tile(int t, int& I, int& J) {
    int p   = t / 65;
    int idx = t - p * 65;
    int na  = 64 - p;
    if (idx < na) { I = p;      J = p + idx; }
    else          { I = 63 - p; J = 63 - p + (idx - na); }
}

// ---------------- Stage 1: fused normalize + pos (reads x1/x2 once) --------
__global__ void normpos_kernel(const float* __restrict__ x1, const float* __restrict__ x2) {
    int i    = blockIdx.x * 8 + (threadIdx.x >> 5);   // pair row 0..4095
    int lane = threadIdx.x & 31;
    if (blockIdx.x == 0 && threadIdx.x == 0) g_done = 0;

    const float4* s1 = reinterpret_cast<const float4*>(x1 + (size_t)i * D);
    const float4* s2 = reinterpret_cast<const float4*>(x2 + (size_t)i * D);
    float4 a0 = s1[lane * 2], a1 = s1[lane * 2 + 1];
    float4 b0 = s2[lane * 2], b1 = s2[lane * 2 + 1];

    float ss1 = a0.x * a0.x + a0.y * a0.y + a0.z * a0.z + a0.w * a0.w
              + a1.x * a1.x + a1.y * a1.y + a1.z * a1.z + a1.w * a1.w;
    float ss2 = b0.x * b0.x + b0.y * b0.y + b0.z * b0.z + b0.w * b0.w
              + b1.x * b1.x + b1.y * b1.y + b1.z * b1.z + b1.w * b1.w;
    float dot = a0.x * b0.x + a0.y * b0.y + a0.z * b0.z + a0.w * b0.w
              + a1.x * b1.x + a1.y * b1.y + a1.z * b1.z + a1.w * b1.w;
    #pragma unroll
    for (int o = 16; o; o >>= 1) {
        ss1 += __shfl_xor_sync(0xffffffffu, ss1, o);
        ss2 += __shfl_xor_sync(0xffffffffu, ss2, o);
        dot += __shfl_xor_sync(0xffffffffu, dot, o);
    }
    float inv1 = 1.0f / fmaxf(sqrtf(ss1), 1e-12f);
    float inv2 = 1.0f / fmaxf(sqrtf(ss2), 1e-12f);
    if (lane == 0) {
        g_pos[i] = dot * inv1 * inv2;
        g_denom[i] = 0.0f;
        g_denom[i + NROWS] = 0.0f;
    }

    uint2 w1, w2;
    w1.x = pack_e4m3x4(a0.x * inv1, a0.y * inv1, a0.z * inv1, a0.w * inv1);
    w1.y = pack_e4m3x4(a1.x * inv1, a1.y * inv1, a1.z * inv1, a1.w * inv1);
    w2.x = pack_e4m3x4(b0.x * inv2, b0.y * inv2, b0.z * inv2, b0.w * inv2);
    w2.y = pack_e4m3x4(b1.x * inv2, b1.y * inv2, b1.z * inv2, b1.w * inv2);
    *reinterpret_cast<uint2*>(g_z8 + (size_t)i * D + lane * 8) = w1;
    *reinterpret_cast<uint2*>(g_z8 + (size_t)(i + NROWS) * D + lane * 8) = w2;
}

// ---------------- tile loader: 128 rows x 256 fp8 (256B/row) ----------------
__device__ __forceinline__ void load_tile(uint32_t dst, int row0, int tid) {
    const unsigned char* src = g_z8 + (size_t)row0 * D;
    #pragma unroll
    for (int i = 0; i < 8; i++) {
        int idx = tid + i * 256;
        int r = idx >> 4, s = idx & 15;
        cp_async16(dst + r * TSTRIDE_B + s * 16, src + r * D + s * 16);
    }
}

// ---------------- Stage 2: triangular fused FP8 GEMM + exp + sums -----------
__global__ __launch_bounds__(256, 1)
void gemm_kernel(float* __restrict__ out) {
    extern __shared__ char smem[];
    const int tid  = threadIdx.x;
    const int lane = tid & 31;
    const int warp = tid >> 5;
    const int wm   = warp >> 2;             // 0..1  (64-row half)
    const int wn   = warp & 3;              // 0..3  (32-col slice)
    const int cta  = blockIdx.x;

    const uint32_t smem_u = smem_to_u32(smem);
    const uint32_t A_base = smem_u;
    const uint32_t Bbuf[2] = { smem_u + TILE_BYTES, smem_u + 2 * TILE_BYTES };

    const int t0 = (cta * NUM_TILES) / NUM_CTAS;
    const int t1 = ((cta + 1) * NUM_TILES) / NUM_CTAS;

    int I, J;
    decode_tile(t0, I, J);
    load_tile(A_base, I * BM, tid);
    load_tile(Bbuf[0], J * BN, tid);
    CP_COMMIT();
    int cur = 0;

    const uint32_t a_off = (uint32_t)((wm * 64 + (lane & 15)) * TSTRIDE_B + (lane >> 4) * 16);
    const uint32_t b_off = (uint32_t)((wn * 32 + (lane & 7)) * TSTRIDE_B + ((lane >> 3) & 1) * 16);

    float denom[8] = {0, 0, 0, 0, 0, 0, 0, 0};

    for (int t = t0; t < t1; t++) {
        int nI = I, nJ = J;
        const bool have = (t + 1 < t1);
        if (have) decode_tile(t + 1, nI, nJ);

        if (have && nI == I) {
            load_tile(Bbuf[cur ^ 1], nJ * BN, tid);
            CP_COMMIT();
            CP_WAIT1();
        } else {
            CP_WAIT0();
        }
        __syncthreads();

        // ---- GEMM: 8 K-steps of k=32 fp8 ----
        const uint32_t Ab = A_base + a_off;
        const uint32_t Bb = Bbuf[cur] + b_off;
        float acc[4][4][4];
        #pragma unroll
        for (int mi = 0; mi < 4; mi++)
            #pragma unroll
            for (int ni = 0; ni < 4; ni++)
                #pragma unroll
                for (int e = 0; e < 4; e++) acc[mi][ni][e] = 0.0f;

        #pragma unroll
        for (int ks = 0; ks < K_STEPS; ks++) {
            uint32_t a[4][4], b[4][2];
            #pragma unroll
            for (int mi = 0; mi < 4; mi++)
                ldsm_x4(a[mi], Ab + mi * (16 * TSTRIDE_B) + ks * 32);
            #pragma unroll
            for (int ni = 0; ni < 4; ni++)
                ldsm_x2(b[ni], Bb + ni * (8 * TSTRIDE_B) + ks * 32);
            #pragma unroll
            for (int mi = 0; mi < 4; mi++)
                #pragma unroll
                for (int ni = 0; ni < 4; ni++)
                    MMA16832F8(acc[mi][ni], a[mi], b[ni]);
        }

        // ---- epilogue: exp; row sums always, col sums when I < J ----
        const bool diag = (I == J);
        const int row0 = I * BM + wm * 64;
        const int col0 = J * BN + wn * 32;
        float cs[8] = {0, 0, 0, 0, 0, 0, 0, 0};
        #pragma unroll
        for (int mi = 0; mi < 4; mi++)
            #pragma unroll
            for (int ni = 0; ni < 4; ni++)
                #pragma unroll
                for (int e = 0; e < 4; e++) {
                    float v = __expf(acc[mi][ni][e] * TAU_INV);
                    if (diag) {
                        int r = row0 + mi * 16 + (e >> 1) * 8 + (lane >> 2);
                        int c = col0 + ni * 8 + (lane & 3) * 2 + (e & 1);
                        if (c == r) v = 1.0f;            // diag -> exp(0)
                    }
                    denom[mi * 2 + (e >> 1)] += v;
                    cs[ni * 2 + (e & 1)] += v;
                }
        if (!diag) {
            // reduce col partials over row-carrying lane bits (2,3,4)
            #pragma unroll
            for (int k = 0; k < 8; k++) {
                cs[k] += __shfl_xor_sync(0xffffffffu, cs[k], 4);
                cs[k] += __shfl_xor_sync(0xffffffffu, cs[k], 8);
                cs[k] += __shfl_xor_sync(0xffffffffu, cs[k], 16);
            }
            if (lane < 4) {
                #pragma unroll
                for (int k = 0; k < 8; k++)
                    atomicAdd(&g_denom[col0 + (k >> 1) * 8 + lane * 2 + (k & 1)], cs[k]);
            }
        }

        // ---- flush row denominators when strip changes (or at end) ----
        if (!have || nI != I) {
            #pragma unroll
            for (int d = 0; d < 8; d++) {
                denom[d] += __shfl_xor_sync(0xffffffffu, denom[d], 1);
                denom[d] += __shfl_xor_sync(0xffffffffu, denom[d], 2);
            }
            if ((lane & 3) == 0) {
                #pragma unroll
                for (int d = 0; d < 8; d++)
                    atomicAdd(&g_denom[row0 + (d >> 1) * 16 + (d & 1) * 8 + (lane >> 2)],
                              denom[d]);
            }
            #pragma unroll
            for (int d = 0; d < 8; d++) denom[d] = 0.0f;
        }

        __syncthreads();   // all warps done with A / Bbuf[cur] before refill

        if (have) {
            if (nI != I) {
                load_tile(A_base, nI * BM, tid);
                load_tile(Bbuf[cur ^ 1], nJ * BN, tid);
                CP_COMMIT();
            }
            cur ^= 1;
            I = nI; J = nJ;
        }
    }

    // ---- last CTA: final log/mean reduction ----
    __threadfence();
    __shared__ unsigned s_tick;
    if (tid == 0) s_tick = atomicAdd(&g_done, 1u);
    __syncthreads();
    if (s_tick == NUM_CTAS - 1) {
        float s = 0.0f;
        for (int r = tid; r < TWO_N; r += 256)
            s += logf(g_denom[r]) - g_pos[r & (NROWS - 1)] * TAU_INV;
        #pragma unroll
        for (int o = 16; o; o >>= 1) s += __shfl_xor_sync(0xffffffffu, s, o);
        __shared__ float red[8];
        if (lane == 0) red[warp] = s;
        __syncthreads();
        if (tid == 0) {
            float v = 0.0f;
            #pragma unroll
            for (int w = 0; w < 8; w++) v += red[w];
            out[0] = v * (1.0f / (float)TWO_N);
        }
    }
}

// ---------------- launch ----------------------------------------------------
extern "C" void kernel_launch(void* const* d_in, const int* in_sizes, int n_in,
                              void* d_out, int out_size) {
    (void)in_sizes; (void)n_in; (void)out_size;
    const float* x1 = (const float*)d_in[0];
    const float* x2 = (const float*)d_in[1];
    float* out = (float*)d_out;

    cudaFuncSetAttribute(gemm_kernel,
                         cudaFuncAttributeMaxDynamicSharedMemorySize, SMEM_TOTAL);

    normpos_kernel<<<NROWS / 8, 256>>>(x1, x2);
    gemm_kernel<<<NUM_CTAS, 256, SMEM_TOTAL>>>(out);
}

// round 5
// speedup vs baseline: 1.0023x; 1.0023x over previous
#include <cuda_runtime.h>
#include <cuda_bf16.h>
#include <cuda_fp8.h>
#include <cstdint>

// ============================================================================
// ContrastiveLoss (N=4096, D=256, tau=0.1)
//   z = normalize(concat(x1,x2)) -> e4m3
//   denom[r] = sum_j exp(mask * (z_r . z_j) / tau)   (diag -> exp(0)=1)
//   loss = mean_r( log(denom[r]) - pos[r]/tau )      (pos in exact fp32)
// Symmetric-triangle fused FP8 mma.sync GEMM, 512 threads/CTA (4x4 warps,
// 32x32 per warp) for 2x issue parallelism vs round-4's 256-thread version.
// ============================================================================

#define TAU_INV 10.0f
static constexpr int NROWS = 4096;
static constexpr int TWO_N = 8192;
static constexpr int D     = 256;          // K
static constexpr int BM    = 128;
static constexpr int BN    = 128;
static constexpr int NSTRIP = TWO_N / BM;            // 64
static constexpr int NUM_TILES = NSTRIP * (NSTRIP + 1) / 2;   // 2080
static constexpr int NUM_CTAS  = 148;
static constexpr int K_STEPS   = D / 32;             // 8 (fp8 k=32 per mma)
static constexpr int NTHREADS  = 512;

// SMEM tiles: [128 rows][256 k] fp8, padded row stride 272 B (17 x 16B)
static constexpr int TSTRIDE_B = 272;
static constexpr int TILE_BYTES = BM * TSTRIDE_B;     // 34816
static constexpr int SMEM_TOTAL = 3 * TILE_BYTES;     // A + B0 + B1 = 104448

// ---------------- device scratch (allocation-free) --------------------------
__device__ unsigned char g_z8[TWO_N * D];   // e4m3, row-major [8192][256]  (2 MB)
__device__ float    g_pos[NROWS];
__device__ float    g_denom[TWO_N];
__device__ unsigned g_done;

// ---------------- PTX helpers ----------------------------------------------
__device__ __forceinline__ uint32_t smem_to_u32(const void* p) {
    uint32_t a;
    asm("{ .reg .u64 t; cvta.to.shared.u64 t, %1; cvt.u32.u64 %0, t; }"
        : "=r"(a) : "l"(p));
    return a;
}

__device__ __forceinline__ void cp_async16(uint32_t dst, const void* src) {
    asm volatile("cp.async.cg.shared.global [%0], [%1], 16;"
                 :: "r"(dst), "l"(src) : "memory");
}
#define CP_COMMIT() asm volatile("cp.async.commit_group;" ::: "memory")
#define CP_WAIT0()  asm volatile("cp.async.wait_group 0;" ::: "memory")
#define CP_WAIT1()  asm volatile("cp.async.wait_group 1;" ::: "memory")

__device__ __forceinline__ void ldsm_x4(uint32_t* r, uint32_t addr) {
    asm volatile("ldmatrix.sync.aligned.m8n8.x4.shared.b16 {%0,%1,%2,%3}, [%4];"
                 : "=r"(r[0]), "=r"(r[1]), "=r"(r[2]), "=r"(r[3]) : "r"(addr));
}
__device__ __forceinline__ void ldsm_x2(uint32_t* r, uint32_t addr) {
    asm volatile("ldmatrix.sync.aligned.m8n8.x2.shared.b16 {%0,%1}, [%2];"
                 : "=r"(r[0]), "=r"(r[1]) : "r"(addr));
}

// FP8 e4m3 MMA: m16n8k32; fragments = bf16-k16 fragments with each b16 lane
// element holding 2 fp8, so ldmatrix b16 addressing carries over unchanged.
#define MMA16832F8(d, a, b) \
    asm volatile( \
        "mma.sync.aligned.m16n8k32.row.col.f32.e4m3.e4m3.f32 " \
        "{%0,%1,%2,%3}, {%4,%5,%6,%7}, {%8,%9}, {%0,%1,%2,%3};" \
        : "+f"((d)[0]), "+f"((d)[1]), "+f"((d)[2]), "+f"((d)[3]) \
        : "r"((a)[0]), "r"((a)[1]), "r"((a)[2]), "r"((a)[3]), \
          "r"((b)[0]), "r"((b)[1]))

__device__ __forceinline__ uint32_t pack_e4m3x4(float v0, float v1, float v2, float v3) {
    __nv_fp8x2_storage_t lo =
        __nv_cvt_float2_to_fp8x2(make_float2(v0, v1), __NV_SATFINITE, __NV_E4M3);
    __nv_fp8x2_storage_t hi =
        __nv_cvt_float2_to_fp8x2(make_float2(v2, v3), __NV_SATFINITE, __NV_E4M3);
    return (uint32_t)lo | ((uint32_t)hi << 16);
}

// Balanced triangle enumeration: pair p in [0,32) = strip p (64-p tiles,
// J=p..63) followed by strip 63-p (p+1 tiles, J=63-p..63). 65 tiles per pair.
__device__ __forceinline__ void decode_tile(int t, int& I, int& J) {
    int p   = t / 65;
    int idx = t - p * 65;
    int na  = 64 - p;
    if (idx < na) { I = p;      J = p + idx; }
    else          { I = 63 - p; J = 63 - p + (idx - na); }
}

// ---------------- Stage 1: fused normalize + pos (reads x1/x2 once) --------
__global__ void normpos_kernel(const float* __restrict__ x1, const float* __restrict__ x2) {
    int i    = blockIdx.x * 8 + (threadIdx.x >> 5);   // pair row 0..4095
    int lane = threadIdx.x & 31;
    if (blockIdx.x == 0 && threadIdx.x == 0) g_done = 0;

    const float4* s1 = reinterpret_cast<const float4*>(x1 + (size_t)i * D);
    const float4* s2 = reinterpret_cast<const float4*>(x2 + (size_t)i * D);
    float4 a0 = s1[lane * 2], a1 = s1[lane * 2 + 1];
    float4 b0 = s2[lane * 2], b1 = s2[lane * 2 + 1];

    float ss1 = a0.x * a0.x + a0.y * a0.y + a0.z * a0.z + a0.w * a0.w
              + a1.x * a1.x + a1.y * a1.y + a1.z * a1.z + a1.w * a1.w;
    float ss2 = b0.x * b0.x + b0.y * b0.y + b0.z * b0.z + b0.w * b0.w
              + b1.x * b1.x + b1.y * b1.y + b1.z * b1.z + b1.w * b1.w;
    float dot = a0.x * b0.x + a0.y * b0.y + a0.z * b0.z + a0.w * b0.w
              + a1.x * b1.x + a1.y * b1.y + a1.z * b1.z + a1.w * b1.w;
    #pragma unroll
    for (int o = 16; o; o >>= 1) {
        ss1 += __shfl_xor_sync(0xffffffffu, ss1, o);
        ss2 += __shfl_xor_sync(0xffffffffu, ss2, o);
        dot += __shfl_xor_sync(0xffffffffu, dot, o);
    }
    float inv1 = 1.0f / fmaxf(sqrtf(ss1), 1e-12f);
    float inv2 = 1.0f / fmaxf(sqrtf(ss2), 1e-12f);
    if (lane == 0) {
        g_pos[i] = dot * inv1 * inv2;
        g_denom[i] = 0.0f;
        g_denom[i + NROWS] = 0.0f;
    }

    uint2 w1, w2;
    w1.x = pack_e4m3x4(a0.x * inv1, a0.y * inv1, a0.z * inv1, a0.w * inv1);
    w1.y = pack_e4m3x4(a1.x * inv1, a1.y * inv1, a1.z * inv1, a1.w * inv1);
    w2.x = pack_e4m3x4(b0.x * inv2, b0.y * inv2, b0.z * inv2, b0.w * inv2);
    w2.y = pack_e4m3x4(b1.x * inv2, b1.y * inv2, b1.z * inv2, b1.w * inv2);
    *reinterpret_cast<uint2*>(g_z8 + (size_t)i * D + lane * 8) = w1;
    *reinterpret_cast<uint2*>(g_z8 + (size_t)(i + NROWS) * D + lane * 8) = w2;
}

// ---------------- tile loader: 128 rows x 256 fp8 (256B/row) ----------------
__device__ __forceinline__ void load_tile(uint32_t dst, int row0, int tid) {
    const unsigned char* src = g_z8 + (size_t)row0 * D;
    #pragma unroll
    for (int i = 0; i < 4; i++) {
        int idx = tid + i * NTHREADS;
        int r = idx >> 4, s = idx & 15;
        cp_async16(dst + r * TSTRIDE_B + s * 16, src + r * D + s * 16);
    }
}

// ---------------- Stage 2: triangular fused FP8 GEMM + exp + sums -----------
__global__ __launch_bounds__(NTHREADS, 1)
void gemm_kernel(float* __restrict__ out) {
    extern __shared__ char smem[];
    const int tid  = threadIdx.x;
    const int lane = tid & 31;
    const int warp = tid >> 5;              // 0..15
    const int wm   = warp >> 2;             // 0..3  (32-row slice)
    const int wn   = warp & 3;              // 0..3  (32-col slice)
    const int cta  = blockIdx.x;

    const uint32_t smem_u = smem_to_u32(smem);
    const uint32_t A_base = smem_u;
    const uint32_t Bbuf[2] = { smem_u + TILE_BYTES, smem_u + 2 * TILE_BYTES };

    const int t0 = (cta * NUM_TILES) / NUM_CTAS;
    const int t1 = ((cta + 1) * NUM_TILES) / NUM_CTAS;

    int I, J;
    decode_tile(t0, I, J);
    load_tile(A_base, I * BM, tid);
    load_tile(Bbuf[0], J * BN, tid);
    CP_COMMIT();
    int cur = 0;

    const uint32_t a_off = (uint32_t)((wm * 32 + (lane & 15)) * TSTRIDE_B + (lane >> 4) * 16);
    const uint32_t b_off = (uint32_t)((wn * 32 + (lane & 7)) * TSTRIDE_B + ((lane >> 3) & 1) * 16);

    float denom[4] = {0, 0, 0, 0};          // [mi][e>>1]

    for (int t = t0; t < t1; t++) {
        int nI = I, nJ = J;
        const bool have = (t + 1 < t1);
        if (have) decode_tile(t + 1, nI, nJ);

        if (have && nI == I) {
            load_tile(Bbuf[cur ^ 1], nJ * BN, tid);
            CP_COMMIT();
            CP_WAIT1();
        } else {
            CP_WAIT0();
        }
        __syncthreads();

        // ---- GEMM: 8 K-steps of k=32 fp8; warp tile 32x32 ----
        const uint32_t Ab = A_base + a_off;
        const uint32_t Bb = Bbuf[cur] + b_off;
        float acc[2][4][4];
        #pragma unroll
        for (int mi = 0; mi < 2; mi++)
            #pragma unroll
            for (int ni = 0; ni < 4; ni++)
                #pragma unroll
                for (int e = 0; e < 4; e++) acc[mi][ni][e] = 0.0f;

        #pragma unroll
        for (int ks = 0; ks < K_STEPS; ks++) {
            uint32_t a[2][4], b[4][2];
            #pragma unroll
            for (int mi = 0; mi < 2; mi++)
                ldsm_x4(a[mi], Ab + mi * (16 * TSTRIDE_B) + ks * 32);
            #pragma unroll
            for (int ni = 0; ni < 4; ni++)
                ldsm_x2(b[ni], Bb + ni * (8 * TSTRIDE_B) + ks * 32);
            #pragma unroll
            for (int mi = 0; mi < 2; mi++)
                #pragma unroll
                for (int ni = 0; ni < 4; ni++)
                    MMA16832F8(acc[mi][ni], a[mi], b[ni]);
        }

        // ---- epilogue: exp; row sums always, col sums when I < J ----
        const bool diag = (I == J);
        const int row0 = I * BM + wm * 32;
        const int col0 = J * BN + wn * 32;
        float cs[8] = {0, 0, 0, 0, 0, 0, 0, 0};
        #pragma unroll
        for (int mi = 0; mi < 2; mi++)
            #pragma unroll
            for (int ni = 0; ni < 4; ni++)
                #pragma unroll
                for (int e = 0; e < 4; e++) {
                    float v = __expf(acc[mi][ni][e] * TAU_INV);
                    if (diag) {
                        int r = row0 + mi * 16 + (e >> 1) * 8 + (lane >> 2);
                        int c = col0 + ni * 8 + (lane & 3) * 2 + (e & 1);
                        if (c == r) v = 1.0f;            // diag -> exp(0)
                    }
                    denom[mi * 2 + (e >> 1)] += v;
                    cs[ni * 2 + (e & 1)] += v;
                }
        if (!diag) {
            // reduce col partials over row-carrying lane bits (2,3,4)
            #pragma unroll
            for (int k = 0; k < 8; k++) {
                cs[k] += __shfl_xor_sync(0xffffffffu, cs[k], 4);
                cs[k] += __shfl_xor_sync(0xffffffffu, cs[k], 8);
                cs[k] += __shfl_xor_sync(0xffffffffu, cs[k], 16);
            }
            if (lane < 4) {
                #pragma unroll
                for (int k = 0; k < 8; k++)
                    atomicAdd(&g_denom[col0 + (k >> 1) * 8 + lane * 2 + (k & 1)], cs[k]);
            }
        }

        // ---- flush row denominators when strip changes (or at end) ----
        if (!have || nI != I) {
            #pragma unroll
            for (int d = 0; d < 4; d++) {
                denom[d] += __shfl_xor_sync(0xffffffffu, denom[d], 1);
                denom[d] += __shfl_xor_sync(0xffffffffu, denom[d], 2);
            }
            if ((lane & 3) == 0) {
                #pragma unroll
                for (int d = 0; d < 4; d++)
                    atomicAdd(&g_denom[row0 + (d >> 1) * 16 + (d & 1) * 8 + (lane >> 2)],
                              denom[d]);
            }
            #pragma unroll
            for (int d = 0; d < 4; d++) denom[d] = 0.0f;
        }

        __syncthreads();   // all warps done with A / Bbuf[cur] before refill

        if (have) {
            if (nI != I) {
                load_tile(A_base, nI * BM, tid);
                load_tile(Bbuf[cur ^ 1], nJ * BN, tid);
                CP_COMMIT();
            }
            cur ^= 1;
            I = nI; J = nJ;
        }
    }

    // ---- last CTA: final log/mean reduction ----
    __threadfence();
    __shared__ unsigned s_tick;
    if (tid == 0) s_tick = atomicAdd(&g_done, 1u);
    __syncthreads();
    if (s_tick == NUM_CTAS - 1) {
        float s = 0.0f;
        for (int r = tid; r < TWO_N; r += NTHREADS)
            s += logf(g_denom[r]) - g_pos[r & (NROWS - 1)] * TAU_INV;
        #pragma unroll
        for (int o = 16; o; o >>= 1) s += __shfl_xor_sync(0xffffffffu, s, o);
        __shared__ float red[16];
        if (lane == 0) red[warp] = s;
        __syncthreads();
        if (tid == 0) {
            float v = 0.0f;
            #pragma unroll
            for (int w = 0; w < 16; w++) v += red[w];
            out[0] = v * (1.0f / (float)TWO_N);
        }
    }
}

// ---------------- launch ----------------------------------------------------
extern "C" void kernel_launch(void* const* d_in, const int* in_sizes, int n_in,
                              void* d_out, int out_size) {
    (void)in_sizes; (void)n_in; (void)out_size;
    const float* x1 = (const float*)d_in[0];
    const float* x2 = (const float*)d_in[1];
    float* out = (float*)d_out;

    cudaFuncSetAttribute(gemm_kernel,
                         cudaFuncAttributeMaxDynamicSharedMemorySize, SMEM_TOTAL);

    normpos_kernel<<<NROWS / 8, 256>>>(x1, x2);
    gemm_kernel<<<NUM_CTAS, NTHREADS, SMEM_TOTAL>>>(out);
}

// round 6
// speedup vs baseline: 1.0491x; 1.0467x over previous
#include <cuda_runtime.h>
#include <cuda_bf16.h>
#include <cuda_fp8.h>
#include <cstdint>

// ============================================================================
// ContrastiveLoss (N=4096, D=256, tau=0.1)
//   z = normalize(concat(x1,x2)) -> e4m3
//   denom[r] = sum_j exp(mask * (z_r . z_j) / tau)   (diag -> exp(0)=1)
//   loss = mean_r( log(denom[r]) - pos[r]/tau )      (pos in exact fp32)
// Symmetric-triangle fused FP8 mma.sync GEMM. 128x64 tiles, 256 thr/CTA,
// 2 CTAs/SM (reg-capped) so one CTA's epilogue overlaps the other's MMA.
// ============================================================================

#define TAU_INV 10.0f
static constexpr int NROWS = 4096;
static constexpr int TWO_N = 8192;
static constexpr int D     = 256;          // K
static constexpr int BM    = 128;          // rows per strip
static constexpr int BN    = 64;           // cols per tile
static constexpr int NSTRIP = TWO_N / BM;            // 64
static constexpr int NCOLT  = TWO_N / BN;            // 128
// tiles with J >= 2I: per strip I -> 128-2I; pair(p, 63-p) -> 130 each
static constexpr int NUM_TILES = 4160;
static constexpr int NUM_CTAS  = 296;                // 2 per SM
static constexpr int K_STEPS   = D / 32;             // 8 (fp8 k=32 per mma)
static constexpr int NTHREADS  = 256;

// SMEM: padded row stride 272 B (17 x 16B)
static constexpr int TSTRIDE_B = 272;
static constexpr int A_TILE_BYTES = BM * TSTRIDE_B;   // 34816
static constexpr int B_TILE_BYTES = BN * TSTRIDE_B;   // 17408
static constexpr int SMEM_TOTAL = A_TILE_BYTES + 2 * B_TILE_BYTES;  // 69632

// ---------------- device scratch (allocation-free) --------------------------
__device__ unsigned char g_z8[TWO_N * D];   // e4m3, row-major [8192][256]  (2 MB)
__device__ float    g_pos[NROWS];
__device__ float    g_denom[TWO_N];
__device__ unsigned g_done;

// ---------------- PTX helpers ----------------------------------------------
__device__ __forceinline__ uint32_t smem_to_u32(const void* p) {
    uint32_t a;
    asm("{ .reg .u64 t; cvta.to.shared.u64 t, %1; cvt.u32.u64 %0, t; }"
        : "=r"(a) : "l"(p));
    return a;
}

__device__ __forceinline__ void cp_async16(uint32_t dst, const void* src) {
    asm volatile("cp.async.cg.shared.global [%0], [%1], 16;"
                 :: "r"(dst), "l"(src) : "memory");
}
#define CP_COMMIT() asm volatile("cp.async.commit_group;" ::: "memory")
#define CP_WAIT0()  asm volatile("cp.async.wait_group 0;" ::: "memory")
#define CP_WAIT1()  asm volatile("cp.async.wait_group 1;" ::: "memory")

__device__ __forceinline__ void ldsm_x4(uint32_t* r, uint32_t addr) {
    asm volatile("ldmatrix.sync.aligned.m8n8.x4.shared.b16 {%0,%1,%2,%3}, [%4];"
                 : "=r"(r[0]), "=r"(r[1]), "=r"(r[2]), "=r"(r[3]) : "r"(addr));
}
__device__ __forceinline__ void ldsm_x2(uint32_t* r, uint32_t addr) {
    asm volatile("ldmatrix.sync.aligned.m8n8.x2.shared.b16 {%0,%1}, [%2];"
                 : "=r"(r[0]), "=r"(r[1]) : "r"(addr));
}

// FP8 e4m3 MMA: m16n8k32; fragments = bf16-k16 fragments with each b16 lane
// element holding 2 fp8, so ldmatrix b16 addressing carries over unchanged.
#define MMA16832F8(d, a, b) \
    asm volatile( \
        "mma.sync.aligned.m16n8k32.row.col.f32.e4m3.e4m3.f32 " \
        "{%0,%1,%2,%3}, {%4,%5,%6,%7}, {%8,%9}, {%0,%1,%2,%3};" \
        : "+f"((d)[0]), "+f"((d)[1]), "+f"((d)[2]), "+f"((d)[3]) \
        : "r"((a)[0]), "r"((a)[1]), "r"((a)[2]), "r"((a)[3]), \
          "r"((b)[0]), "r"((b)[1]))

__device__ __forceinline__ uint32_t pack_e4m3x4(float v0, float v1, float v2, float v3) {
    __nv_fp8x2_storage_t lo =
        __nv_cvt_float2_to_fp8x2(make_float2(v0, v1), __NV_SATFINITE, __NV_E4M3);
    __nv_fp8x2_storage_t hi =
        __nv_cvt_float2_to_fp8x2(make_float2(v2, v3), __NV_SATFINITE, __NV_E4M3);
    return (uint32_t)lo | ((uint32_t)hi << 16);
}

// Balanced enumeration: pair p in [0,32) = strip p (J=2p..127, 128-2p tiles)
// then strip 63-p (J=126-2p..127, 2p+2 tiles). 130 tiles per pair.
__device__ __forceinline__ void decode_tile(int t, int& I, int& J) {
    int p   = t / 130;
    int idx = t - p * 130;
    int na  = 128 - 2 * p;
    if (idx < na) { I = p;      J = 2 * p + idx; }
    else          { I = 63 - p; J = 126 - 2 * p + (idx - na); }
}

// ---------------- Stage 1: fused normalize + pos (reads x1/x2 once) --------
__global__ void normpos_kernel(const float* __restrict__ x1, const float* __restrict__ x2) {
    int i    = blockIdx.x * 8 + (threadIdx.x >> 5);   // pair row 0..4095
    int lane = threadIdx.x & 31;
    if (blockIdx.x == 0 && threadIdx.x == 0) g_done = 0;

    const float4* s1 = reinterpret_cast<const float4*>(x1 + (size_t)i * D);
    const float4* s2 = reinterpret_cast<const float4*>(x2 + (size_t)i * D);
    float4 a0 = s1[lane * 2], a1 = s1[lane * 2 + 1];
    float4 b0 = s2[lane * 2], b1 = s2[lane * 2 + 1];

    float ss1 = a0.x * a0.x + a0.y * a0.y + a0.z * a0.z + a0.w * a0.w
              + a1.x * a1.x + a1.y * a1.y + a1.z * a1.z + a1.w * a1.w;
    float ss2 = b0.x * b0.x + b0.y * b0.y + b0.z * b0.z + b0.w * b0.w
              + b1.x * b1.x + b1.y * b1.y + b1.z * b1.z + b1.w * b1.w;
    float dot = a0.x * b0.x + a0.y * b0.y + a0.z * b0.z + a0.w * b0.w
              + a1.x * b1.x + a1.y * b1.y + a1.z * b1.z + a1.w * b1.w;
    #pragma unroll
    for (int o = 16; o; o >>= 1) {
        ss1 += __shfl_xor_sync(0xffffffffu, ss1, o);
        ss2 += __shfl_xor_sync(0xffffffffu, ss2, o);
        dot += __shfl_xor_sync(0xffffffffu, dot, o);
    }
    float inv1 = 1.0f / fmaxf(sqrtf(ss1), 1e-12f);
    float inv2 = 1.0f / fmaxf(sqrtf(ss2), 1e-12f);
    if (lane == 0) {
        g_pos[i] = dot * inv1 * inv2;
        g_denom[i] = 0.0f;
        g_denom[i + NROWS] = 0.0f;
    }

    uint2 w1, w2;
    w1.x = pack_e4m3x4(a0.x * inv1, a0.y * inv1, a0.z * inv1, a0.w * inv1);
    w1.y = pack_e4m3x4(a1.x * inv1, a1.y * inv1, a1.z * inv1, a1.w * inv1);
    w2.x = pack_e4m3x4(b0.x * inv2, b0.y * inv2, b0.z * inv2, b0.w * inv2);
    w2.y = pack_e4m3x4(b1.x * inv2, b1.y * inv2, b1.z * inv2, b1.w * inv2);
    *reinterpret_cast<uint2*>(g_z8 + (size_t)i * D + lane * 8) = w1;
    *reinterpret_cast<uint2*>(g_z8 + (size_t)(i + NROWS) * D + lane * 8) = w2;
}

// ---------------- tile loaders (fp8 rows of 256 B) ---------------------------
__device__ __forceinline__ void load_rows(uint32_t dst, int row0, int nrows, int tid) {
    const unsigned char* src = g_z8 + (size_t)row0 * D;
    int total = nrows * 16;                 // 16-byte chunks
    #pragma unroll
    for (int i = 0; i < 8; i++) {
        int idx = tid + i * NTHREADS;
        if (idx < total) {
            int r = idx >> 4, s = idx & 15;
            cp_async16(dst + r * TSTRIDE_B + s * 16, src + r * D + s * 16);
        }
    }
}
__device__ __forceinline__ void load_A(uint32_t dst, int row0, int tid) {
    const unsigned char* src = g_z8 + (size_t)row0 * D;
    #pragma unroll
    for (int i = 0; i < 8; i++) {
        int idx = tid + i * NTHREADS;      // 2048 chunks
        int r = idx >> 4, s = idx & 15;
        cp_async16(dst + r * TSTRIDE_B + s * 16, src + r * D + s * 16);
    }
}
__device__ __forceinline__ void load_B(uint32_t dst, int row0, int tid) {
    const unsigned char* src = g_z8 + (size_t)row0 * D;
    #pragma unroll
    for (int i = 0; i < 4; i++) {
        int idx = tid + i * NTHREADS;      // 1024 chunks
        int r = idx >> 4, s = idx & 15;
        cp_async16(dst + r * TSTRIDE_B + s * 16, src + r * D + s * 16);
    }
}

// ---------------- Stage 2: triangular fused FP8 GEMM + exp + sums -----------
__global__ __launch_bounds__(NTHREADS, 2)
void gemm_kernel(float* __restrict__ out) {
    extern __shared__ char smem[];
    const int tid  = threadIdx.x;
    const int lane = tid & 31;
    const int warp = tid >> 5;              // 0..7
    const int wm   = warp >> 1;             // 0..3  (32-row slice)
    const int wn   = warp & 1;              // 0..1  (32-col slice)
    const int cta  = blockIdx.x;

    const uint32_t smem_u = smem_to_u32(smem);
    const uint32_t A_base = smem_u;
    const uint32_t Bbuf[2] = { smem_u + A_TILE_BYTES,
                               smem_u + A_TILE_BYTES + B_TILE_BYTES };

    const int t0 = (int)(((long long)cta * NUM_TILES) / NUM_CTAS);
    const int t1 = (int)(((long long)(cta + 1) * NUM_TILES) / NUM_CTAS);

    int I, J;
    decode_tile(t0, I, J);
    load_A(A_base, I * BM, tid);
    load_B(Bbuf[0], J * BN, tid);
    CP_COMMIT();
    int cur = 0;

    const uint32_t a_off = (uint32_t)((wm * 32 + (lane & 15)) * TSTRIDE_B + (lane >> 4) * 16);
    const uint32_t b_off = (uint32_t)((wn * 32 + (lane & 7)) * TSTRIDE_B + ((lane >> 3) & 1) * 16);

    float denom[4] = {0, 0, 0, 0};          // [mi][e>>1]

    for (int t = t0; t < t1; t++) {
        int nI = I, nJ = J;
        const bool have = (t + 1 < t1);
        if (have) decode_tile(t + 1, nI, nJ);

        if (have && nI == I) {
            load_B(Bbuf[cur ^ 1], nJ * BN, tid);
            CP_COMMIT();
            CP_WAIT1();
        } else {
            CP_WAIT0();
        }
        __syncthreads();

        // ---- GEMM: 8 K-steps of k=32 fp8; warp tile 32x32 ----
        const uint32_t Ab = A_base + a_off;
        const uint32_t Bb = Bbuf[cur] + b_off;
        float acc[2][4][4];
        #pragma unroll
        for (int mi = 0; mi < 2; mi++)
            #pragma unroll
            for (int ni = 0; ni < 4; ni++)
                #pragma unroll
                for (int e = 0; e < 4; e++) acc[mi][ni][e] = 0.0f;

        #pragma unroll
        for (int ks = 0; ks < K_STEPS; ks++) {
            uint32_t a[2][4], b[4][2];
            #pragma unroll
            for (int mi = 0; mi < 2; mi++)
                ldsm_x4(a[mi], Ab + mi * (16 * TSTRIDE_B) + ks * 32);
            #pragma unroll
            for (int ni = 0; ni < 4; ni++)
                ldsm_x2(b[ni], Bb + ni * (8 * TSTRIDE_B) + ks * 32);
            #pragma unroll
            for (int mi = 0; mi < 2; mi++)
                #pragma unroll
                for (int ni = 0; ni < 4; ni++)
                    MMA16832F8(acc[mi][ni], a[mi], b[ni]);
        }

        // ---- epilogue: exp; row sums always, col sums when above diag blk ---
        const bool diagblk = ((J >> 1) == I);
        const int row0 = I * BM + wm * 32;
        const int col0 = J * BN + wn * 32;
        float cs[8] = {0, 0, 0, 0, 0, 0, 0, 0};
        #pragma unroll
        for (int mi = 0; mi < 2; mi++)
            #pragma unroll
            for (int ni = 0; ni < 4; ni++)
                #pragma unroll
                for (int e = 0; e < 4; e++) {
                    float v = __expf(acc[mi][ni][e] * TAU_INV);
                    if (diagblk) {
                        int r = row0 + mi * 16 + (e >> 1) * 8 + (lane >> 2);
                        int c = col0 + ni * 8 + (lane & 3) * 2 + (e & 1);
                        if (c == r) v = 1.0f;            // diag -> exp(0)
                    }
                    denom[mi * 2 + (e >> 1)] += v;
                    cs[ni * 2 + (e & 1)] += v;
                }
        if (!diagblk) {
            // reduce col partials over row-carrying lane bits (2,3,4)
            #pragma unroll
            for (int k = 0; k < 8; k++) {
                cs[k] += __shfl_xor_sync(0xffffffffu, cs[k], 4);
                cs[k] += __shfl_xor_sync(0xffffffffu, cs[k], 8);
                cs[k] += __shfl_xor_sync(0xffffffffu, cs[k], 16);
            }
            if (lane < 4) {
                #pragma unroll
                for (int k = 0; k < 8; k++)
                    atomicAdd(&g_denom[col0 + (k >> 1) * 8 + lane * 2 + (k & 1)], cs[k]);
            }
        }

        // ---- flush row denominators when strip changes (or at end) ----
        if (!have || nI != I) {
            #pragma unroll
            for (int d = 0; d < 4; d++) {
                denom[d] += __shfl_xor_sync(0xffffffffu, denom[d], 1);
                denom[d] += __shfl_xor_sync(0xffffffffu, denom[d], 2);
            }
            if ((lane & 3) == 0) {
                #pragma unroll
                for (int d = 0; d < 4; d++)
                    atomicAdd(&g_denom[row0 + (d >> 1) * 16 + (d & 1) * 8 + (lane >> 2)],
                              denom[d]);
            }
            #pragma unroll
            for (int d = 0; d < 4; d++) denom[d] = 0.0f;
        }

        __syncthreads();   // all warps done with A / Bbuf[cur] before refill

        if (have) {
            if (nI != I) {
                load_A(A_base, nI * BM, tid);
                load_B(Bbuf[cur ^ 1], nJ * BN, tid);
                CP_COMMIT();
            }
            cur ^= 1;
            I = nI; J = nJ;
        }
    }

    // ---- last CTA: final log/mean reduction ----
    __threadfence();
    __shared__ unsigned s_tick;
    if (tid == 0) s_tick = atomicAdd(&g_done, 1u);
    __syncthreads();
    if (s_tick == NUM_CTAS - 1) {
        float s = 0.0f;
        for (int r = tid; r < TWO_N; r += NTHREADS)
            s += logf(g_denom[r]) - g_pos[r & (NROWS - 1)] * TAU_INV;
        #pragma unroll
        for (int o = 16; o; o >>= 1) s += __shfl_xor_sync(0xffffffffu, s, o);
        __shared__ float red[8];
        if (lane == 0) red[warp] = s;
        __syncthreads();
        if (tid == 0) {
            float v = 0.0f;
            #pragma unroll
            for (int w = 0; w < 8; w++) v += red[w];
            out[0] = v * (1.0f / (float)TWO_N);
        }
    }
}

// ---------------- launch ----------------------------------------------------
extern "C" void kernel_launch(void* const* d_in, const int* in_sizes, int n_in,
                              void* d_out, int out_size) {
    (void)in_sizes; (void)n_in; (void)out_size;
    const float* x1 = (const float*)d_in[0];
    const float* x2 = (const float*)d_in[1];
    float* out = (float*)d_out;

    cudaFuncSetAttribute(gemm_kernel,
                         cudaFuncAttributeMaxDynamicSharedMemorySize, SMEM_TOTAL);

    normpos_kernel<<<NROWS / 8, 256>>>(x1, x2);
    gemm_kernel<<<NUM_CTAS, NTHREADS, SMEM_TOTAL>>>(out);
}